// round 10
// baseline (speedup 1.0000x reference)
#include <cuda_runtime.h>
#include <math.h>

typedef unsigned long long ull;

// Problem constants
static constexpr int BN = 4;            // batch
static constexpr int NC = 21;           // classes
static constexpr int H  = 512;
static constexpr int W  = 512;
static constexpr int P  = 171;          // pooled H/W
static constexpr int NH = 169;          // cropped size P - (radius-1)
static constexpr int NPROB = BN * NC;   // 84
static constexpr int MM = NH * NH;      // 28561
static constexpr double D_ALPHA = 5e-4;
static constexpr float  CLIP_MIN = 1e-6f;
static constexpr int SPITCH = 172;      // smem pitch (floats, mult of 4)
static constexpr int SH = 16;           // strip height for k_cov
static constexpr int NSTRIP = (NH + SH - 1) / SH;  // 11

// Scratch (static device globals: no allocation allowed)
__device__ float  g_la[NPROB * P * P];      // pooled one-hot labels
__device__ float  g_pr[NPROB * P * P];      // pooled probs
__device__ double g_S[NPROB * 18 * 18];     // raw second-moment Gram
__device__ double g_sums[NPROB * 18];       // raw first moments
__device__ double g_bce;
__device__ double g_valid;

// stream-pair-block map: 6 lower-tri pairs of the 3 stream-groups
__constant__ int c_PBI[6] = {0, 1, 1, 2, 2, 2};
__constant__ int c_PBJ[6] = {0, 0, 1, 0, 1, 2};

// ---------------------------------------------------------------------------
__global__ void k_init() {
    int i = blockIdx.x * blockDim.x + threadIdx.x;
    if (i < NPROB * 18 * 18) g_S[i] = 0.0;
    if (i < NPROB * 18)      g_sums[i] = 0.0;
    if (i == 0) { g_bce = 0.0; g_valid = 0.0; }
}

// ---------------------------------------------------------------------------
// Fused: BCE partials + sigmoid + one-hot + 3x3/s3/p1 maxpool (R4 champion
// version). Sigmoid monotone -> pooled prob = sigmoid(max valid logit)+1e-6.
__global__ void __launch_bounds__(192) k_pool_bce(const float* __restrict__ logits,
                                                  const int*   __restrict__ labels) {
    int py = blockIdx.x;        // 0..170
    int n  = blockIdx.y;        // 0..3
    int tid = threadIdx.x;

    __shared__ __align__(16) float slog[3][520];   // data at idx 4..515
    __shared__ float smk[3][520];
    __shared__ int   slab[3][520];
    __shared__ float warp_b[6], warp_v[6];

    int y0 = py * 3 - 1;
    const int* lb = labels + (long)n * H * W;

    for (int i = tid; i < 3 * 520; i += 192) {
        int r = i / 520, x = i - r * 520;
        int xx = x - 4;
        int y  = y0 + r;
        bool v = ((unsigned)y < (unsigned)H) && ((unsigned)xx < (unsigned)W);
        int  l = v ? lb[y * W + xx] : NC;
        slab[r][x] = l;
        smk[r][x]  = (l < NC) ? 1.f : 0.f;
    }
    if (tid < 24) {
        int r = tid / 8, j = tid - r * 8;
        int x = (j < 4) ? j : 512 + j;
        slog[r][x] = 0.f;
    }
    __syncthreads();

    int  px  = tid;
    bool act = px < P;
    float mk[9]; int lab[9];
    float valid_part = 0.f, bce_part = 0.f;
    if (act) {
#pragma unroll
        for (int k = 0; k < 9; k++) {
            int r = k / 3, dx = k % 3;
            int idx = 3 * px + 3 + dx;
            mk[k]  = smk[r][idx];
            lab[k] = slab[r][idx];
            valid_part += mk[k];
        }
    }
    bool rv[3];
#pragma unroll
    for (int r = 0; r < 3; r++) rv[r] = (unsigned)(y0 + r) < (unsigned)H;

    long ppp = (long)P * P;
    for (int c = 0; c < NC; c++) {
        __syncthreads();
        const float* lg = logits + (long)(n * NC + c) * H * W;
        for (int i = tid; i < 384; i += 192) {
            int r = i >> 7, j = i & 127;
            float4 v = make_float4(0.f, 0.f, 0.f, 0.f);
            if (rv[r]) v = ((const float4*)(lg + (long)(y0 + r) * W))[j];
            *(float4*)(&slog[r][4 + 4 * j]) = v;
        }
        __syncthreads();
        if (act) {
            float mla = 0.f, mv = -1e30f;
#pragma unroll
            for (int k = 0; k < 9; k++) {
                int r = k / 3, dx = k % 3;
                float xv = slog[r][3 * px + 3 + dx];
                float m  = mk[k];
                float t1 = (lab[k] == c) ? m : 0.f;
                float ax = fabsf(xv);
                float e  = __expf(-ax);
                bce_part += (fmaxf(xv, 0.f) - xv * t1 + __logf(1.f + e)) * m;
                mla = fmaxf(mla, t1);
                mv  = fmaxf(mv, (m > 0.f) ? xv : -1e30f);
            }
            float em  = __expf(-fabsf(mv));
            float rc  = __fdividef(1.f, 1.f + em);
            float sig = (mv >= 0.f) ? rc : em * rc;   // mv=-1e30 -> 0
            long o = (long)(n * NC + c) * ppp + (long)py * P + px;
            g_la[o] = mla;
            g_pr[o] = sig + CLIP_MIN;
        }
    }

#pragma unroll
    for (int off = 16; off > 0; off >>= 1) {
        bce_part   += __shfl_down_sync(0xffffffffu, bce_part,   off);
        valid_part += __shfl_down_sync(0xffffffffu, valid_part, off);
    }
    int wid = tid >> 5, lane = tid & 31;
    if (lane == 0) { warp_b[wid] = bce_part; warp_v[wid] = valid_part; }
    __syncthreads();
    if (tid == 0) {
        float b = 0.f, v = 0.f;
#pragma unroll
        for (int w = 0; w < 6; w++) { b += warp_b[w]; v += warp_v[w]; }
        atomicAdd(&g_bce,   (double)b);
        atomicAdd(&g_valid, (double)v);
    }
}

// ---------------------------------------------------------------------------
// f32x2 helpers
__device__ __forceinline__ ull pk2(float lo, float hi) {
    ull r; asm("mov.b64 %0, {%1, %2};" : "=l"(r) : "f"(lo), "f"(hi)); return r;
}
#define FMA2(d, a, b) asm("fma.rn.f32x2 %0, %1, %2, %0;" : "+l"(d) : "l"(a), "l"(b))

// One step: acc[j*9+l*3+m] += PA[l-pos] * dup(Bj[m-pos])
#define DOSTEP(PL0, PL1, PL2, B00, B01, B02, B10, B11, B12) do {              \
    ull d00 = pk2((B00),(B00)), d01 = pk2((B01),(B01)), d02 = pk2((B02),(B02)); \
    ull d10 = pk2((B10),(B10)), d11 = pk2((B11),(B11)), d12 = pk2((B12),(B12)); \
    FMA2(acc[0],  PL0, d00); FMA2(acc[1],  PL0, d01); FMA2(acc[2],  PL0, d02); \
    FMA2(acc[3],  PL1, d00); FMA2(acc[4],  PL1, d01); FMA2(acc[5],  PL1, d02); \
    FMA2(acc[6],  PL2, d00); FMA2(acc[7],  PL2, d01); FMA2(acc[8],  PL2, d02); \
    FMA2(acc[9],  PL0, d10); FMA2(acc[10], PL0, d11); FMA2(acc[11], PL0, d12); \
    FMA2(acc[12], PL1, d10); FMA2(acc[13], PL1, d11); FMA2(acc[14], PL1, d12); \
    FMA2(acc[15], PL2, d10); FMA2(acc[16], PL2, d11); FMA2(acc[17], PL2, d12); \
} while (0)

#define PAW(t) ((t) < 4 ? PA[(t)]  : PAn[(t) - 4])
#define B0W(t) ((t) < 4 ? b0c[(t)] : b0n[(t) - 4])
#define B1W(t) ((t) < 4 ? b1c[(t)] : b1n[(t) - 4])

// Gram matrix of the 18 shifted views via 6 stream-pair-blocks; also folds in
// the per-view first-moment sums (row-total minus edges trick).
__global__ void __launch_bounds__(96, 6) k_cov() {
    int p     = blockIdx.x;
    int strip = blockIdx.y;
    int ys = strip * SH;
    int sh = min(SH, NH - ys);

    __shared__ __align__(16) float sbuf[2 * 18 * SPITCH];  // la rows | pr rows
    __shared__ float srs[36];
    float* sla = sbuf;
    float* spr = sbuf + 18 * SPITCH;

    int tid = threadIdx.x;
    int row = tid & 15;
    int pb  = tid >> 4;
    const float* la = g_la + p * P * P;
    const float* pr = g_pr + p * P * P;

    int nrows = sh + 2;
    for (int i = tid; i < nrows * P; i += 96) {
        int r = i / P, x = i - r * P;
        sla[r * SPITCH + x] = la[(ys + r) * P + x];
        spr[r * SPITCH + x] = pr[(ys + r) * P + x];
    }
    __syncthreads();

    ull acc[18];
#pragma unroll
    for (int k = 0; k < 18; k++) acc[k] = 0ULL;

    if (row < sh) {
        int gi = c_PBI[pb], gj = c_PBJ[pb];
        int sA0 = 2 * gi, sA1 = 2 * gi + 1, sB0 = 2 * gj, sB1 = 2 * gj + 1;
        const float* pA0 = ((sA0 < 3) ? sla : spr) + ((sA0 < 3 ? sA0 : sA0 - 3) + row) * SPITCH;
        const float* pA1 = ((sA1 < 3) ? sla : spr) + ((sA1 < 3 ? sA1 : sA1 - 3) + row) * SPITCH;
        const float* pB0 = ((sB0 < 3) ? sla : spr) + ((sB0 < 3 ? sB0 : sB0 - 3) + row) * SPITCH;
        const float* pB1 = ((sB1 < 3) ? sla : spr) + ((sB1 < 3 ? sB1 : sB1 - 3) + row) * SPITCH;

        float4 va = *(const float4*)(pA0);
        float4 vb = *(const float4*)(pA1);
        ull PA[4] = { pk2(va.x, vb.x), pk2(va.y, vb.y), pk2(va.z, vb.z), pk2(va.w, vb.w) };
        float4 v0 = *(const float4*)(pB0);
        float4 v1 = *(const float4*)(pB1);
        float b0c[4] = { v0.x, v0.y, v0.z, v0.w };
        float b1c[4] = { v1.x, v1.y, v1.z, v1.w };

        for (int x = 0; x + 4 <= NH - 1; x += 4) {   // steps 0..167
            va = *(const float4*)(pA0 + x + 4);
            vb = *(const float4*)(pA1 + x + 4);
            ull PAn[4] = { pk2(va.x, vb.x), pk2(va.y, vb.y), pk2(va.z, vb.z), pk2(va.w, vb.w) };
            v0 = *(const float4*)(pB0 + x + 4);
            v1 = *(const float4*)(pB1 + x + 4);
            float b0n[4] = { v0.x, v0.y, v0.z, v0.w };
            float b1n[4] = { v1.x, v1.y, v1.z, v1.w };
#pragma unroll
            for (int s = 0; s < 4; s++)
                DOSTEP(PAW(s), PAW(s + 1), PAW(s + 2),
                       B0W(s), B0W(s + 1), B0W(s + 2),
                       B1W(s), B1W(s + 1), B1W(s + 2));
#pragma unroll
            for (int t = 0; t < 4; t++) { PA[t] = PAn[t]; b0c[t] = b0n[t]; b1c[t] = b1n[t]; }
        }
        // tail step x = 168 (positions 168..170)
        DOSTEP(PA[0], PA[1], PA[2], b0c[0], b0c[1], b0c[2], b1c[0], b1c[1], b1c[2]);
    }

    // ---- folded first-moment sums (row totals minus edge elements) ----
    if (tid < 36) {
        int mp = tid / 18, r = tid % 18;
        float T = 0.f;
        if (r < sh + 2) {
            const float* rowp = (mp ? spr : sla) + r * SPITCH;
            for (int x = 0; x < P; x++) T += rowp[x];
        }
        srs[tid] = T;
    }
    __syncthreads();
    if (tid < 18) {
        int mp = tid / 9, dd = tid % 9, dy = dd / 3, dx = dd % 3;
        const float* base = mp ? spr : sla;
        float part = 0.f;
        for (int yl = 0; yl < sh; yl++) {
            int r = yl + dy;
            const float* rowp = base + r * SPITCH;
            float T = srs[mp * 18 + r];
            float rs = (dx == 0) ? T - rowp[169] - rowp[170]
                     : (dx == 1) ? T - rowp[0]   - rowp[170]
                     :             T - rowp[0]   - rowp[1];
            part += rs;
        }
        atomicAdd(&g_sums[p * 18 + tid], (double)part);
    }
    __syncthreads();

    // ---- reduce 96x36 partials over the 16 rows, flush to g_S ----
    float* red = sbuf;             // overlay (96*36 floats)
#pragma unroll
    for (int k = 0; k < 18; k++) {
        float lo, hi;
        asm("mov.b64 {%0, %1}, %2;" : "=f"(lo), "=f"(hi) : "l"(acc[k]));
        red[tid * 36 + k]      = lo;   // i = 0 (stream 2gi)
        red[tid * 36 + 18 + k] = hi;   // i = 1 (stream 2gi+1)
    }
    __syncthreads();
    for (int o = tid; o < 216; o += 96) {
        int pb2 = o / 36, q = o % 36;
        float ssum = 0.f;
#pragma unroll
        for (int r2 = 0; r2 < 16; r2++) ssum += red[(pb2 * 16 + r2) * 36 + q];
        int i = q / 18, k = q % 18;
        int j = k / 9, l = (k % 9) / 3, m = k % 3;
        int a = (2 * c_PBI[pb2] + i) * 3 + l;
        int b = (2 * c_PBJ[pb2] + j) * 3 + m;
        atomicAdd(&g_S[p * 324 + a * 18 + b], (double)ssum);
    }
}

// ---------------------------------------------------------------------------
// One THREAD per (n,c): joint 18x18 Cholesky in registers/local. Ordering:
// dims 0..8 = pr (+alpha diag), 9..17 = la. After eliminating the first 9
// columns the trailing block is appro_var; inject +alpha and continue; sum of
// log of trailing diag = 0.5*logdet(appro_var + alpha I). One 128-thread
// block (power-of-2 reduction!) also produces the final loss.
__global__ void __launch_bounds__(128) k_solve_final(float* __restrict__ out) {
    int t = threadIdx.x;
    double lsum = 0.0;
    if (t < NPROB) {
        const double* S  = g_S    + t * 324;
        const double* sm = g_sums + t * 18;
        double sums[18];
#pragma unroll
        for (int i = 0; i < 18; i++) sums[i] = sm[i];
        const double invM = 1.0 / (double)MM;
        float L[171];
#pragma unroll
        for (int i = 0; i < 18; i++) {
#pragma unroll
            for (int j = 0; j <= i; j++) {
                int oa = (i < 9) ? 9 + i : i - 9;
                int ob = (j < 9) ? 9 + j : j - 9;
                int hi = oa > ob ? oa : ob, lo = oa > ob ? ob : oa;
                double v = S[hi * 18 + lo] - sums[oa] * sums[ob] * invM;
                if (i == j && i < 9) v += D_ALPHA;
                L[i * (i + 1) / 2 + j] = (float)v;
            }
        }
        float ls = 0.f;
#pragma unroll
        for (int k = 0; k < 18; k++) {
            if (k == 9) {      // trailing block now = appro_var; add alpha I
#pragma unroll
                for (int d = 9; d < 18; d++) L[d * (d + 1) / 2 + d] += (float)D_ALPHA;
            }
            float dk = sqrtf(L[k * (k + 1) / 2 + k]);
            if (k >= 9) ls += logf(dk);
            float rd = __fdividef(1.f, dk);
#pragma unroll
            for (int i2 = k + 1; i2 < 18; i2++) L[i2 * (i2 + 1) / 2 + k] *= rd;
#pragma unroll
            for (int j2 = k + 1; j2 < 18; j2++) {
                float ljk = L[j2 * (j2 + 1) / 2 + k];
#pragma unroll
                for (int i2 = j2; i2 < 18; i2++)
                    L[i2 * (i2 + 1) / 2 + j2] -= L[i2 * (i2 + 1) / 2 + k] * ljk;
            }
        }
        lsum = (double)ls;
    }
    // power-of-2 block reduction over 128 slots (FIXED vs R5's 96-thread bug)
    __shared__ double sr[128];
    sr[t] = lsum;
    __syncthreads();
#pragma unroll
    for (int s = 64; s > 0; s >>= 1) {
        if (t < s) sr[t] += sr[t + s];
        __syncthreads();
    }
    if (t == 0) {
        double rmi = sr[0] / 36.0;                  // mean over batch(4)/half_d(9)
        double bce = g_bce / (g_valid + 1.0);
        out[0] = (float)(0.5 * bce + 0.5 * rmi);
    }
}

// ---------------------------------------------------------------------------
extern "C" void kernel_launch(void* const* d_in, const int* in_sizes, int n_in,
                              void* d_out, int out_size) {
    const float* logits = (const float*)d_in[0];
    const int*   labels = (const int*)d_in[1];
    float* out = (float*)d_out;

    k_init<<<(NPROB * 324 + 255) / 256, 256>>>();
    k_pool_bce<<<dim3(P, BN), 192>>>(logits, labels);
    k_cov<<<dim3(NPROB, NSTRIP), 96>>>();
    k_solve_final<<<1, 128>>>(out);
}

// round 11
// speedup vs baseline: 1.1582x; 1.1582x over previous
#include <cuda_runtime.h>
#include <math.h>

typedef unsigned long long ull;

// Problem constants
static constexpr int BN = 4;            // batch
static constexpr int NC = 21;           // classes
static constexpr int H  = 512;
static constexpr int W  = 512;
static constexpr int P  = 171;          // pooled H/W
static constexpr int NH = 169;          // cropped size P - (radius-1)
static constexpr int NPROB = BN * NC;   // 84
static constexpr int MM = NH * NH;      // 28561
static constexpr double D_ALPHA = 5e-4;
static constexpr float  CLIP_MIN = 1e-6f;
static constexpr int SPITCH = 172;      // smem pitch (floats, mult of 4)
static constexpr int SH = 16;           // strip height for k_cov
static constexpr int NSTRIP = (NH + SH - 1) / SH;  // 11
static constexpr int NBLK = P * BN;     // 684 pool blocks

// Scratch (static device globals: no allocation allowed)
__device__ float  g_la[NPROB * P * P];      // pooled one-hot labels
__device__ float  g_pr[NPROB * P * P];      // pooled probs
__device__ double g_S[NPROB * 18 * 18];     // raw second-moment Gram
__device__ double g_sums[NPROB * 18];       // raw first moments
__device__ float2 g_part[NBLK];             // per-block (bce, valid) - plain stores
__device__ double g_rmi[NPROB];

// stream-pair-block map: 6 lower-tri pairs of the 3 stream-groups
__constant__ int c_PBI[6] = {0, 1, 1, 2, 2, 2};
__constant__ int c_PBJ[6] = {0, 0, 1, 0, 1, 2};

// ---------------------------------------------------------------------------
// Fused: BCE partials + sigmoid + one-hot + 3x3/s3/p1 maxpool. Also zeroes
// the g_S/g_sums slices consumed by later kernels (684 x 42 covers exactly).
// MUFU diet: sum of 9 softplus logs batched as ONE log of the product of
// (1+e^-|x|) terms (each in (1,2], product <= 512 -> exact range, safe).
__global__ void __launch_bounds__(192) k_pool_bce(const float* __restrict__ logits,
                                                  const int*   __restrict__ labels) {
    int py = blockIdx.x;        // 0..170
    int n  = blockIdx.y;        // 0..3
    int tid = threadIdx.x;
    int bid = n * P + py;

    // zero scratch consumed by k_cov (684 blocks x 42 = 28728 doubles exact)
    if (tid < 42) {
        int zi = bid * 42 + tid;
        if (zi < NPROB * 324) g_S[zi] = 0.0;
        else                  g_sums[zi - NPROB * 324] = 0.0;
    }

    __shared__ __align__(16) float slog[3][520];   // data at idx 4..515
    __shared__ float smk[3][520];
    __shared__ int   slab[3][520];
    __shared__ float warp_b[6], warp_v[6];

    int y0 = py * 3 - 1;
    const int* lb = labels + (long)n * H * W;

    for (int i = tid; i < 3 * 520; i += 192) {
        int r = i / 520, x = i - r * 520;
        int xx = x - 4;
        int y  = y0 + r;
        bool v = ((unsigned)y < (unsigned)H) && ((unsigned)xx < (unsigned)W);
        int  l = v ? lb[y * W + xx] : NC;
        slab[r][x] = l;
        smk[r][x]  = (l < NC) ? 1.f : 0.f;
    }
    if (tid < 24) {
        int r = tid / 8, j = tid - r * 8;
        int x = (j < 4) ? j : 512 + j;
        slog[r][x] = 0.f;
    }
    __syncthreads();

    int  px  = tid;
    bool act = px < P;
    float mk[9]; int lab[9];
    float valid_part = 0.f, bce_part = 0.f;
    if (act) {
#pragma unroll
        for (int k = 0; k < 9; k++) {
            int r = k / 3, dx = k % 3;
            int idx = 3 * px + 3 + dx;
            mk[k]  = smk[r][idx];
            lab[k] = slab[r][idx];
            valid_part += mk[k];
        }
    }
    bool rv[3];
#pragma unroll
    for (int r = 0; r < 3; r++) rv[r] = (unsigned)(y0 + r) < (unsigned)H;

    long ppp = (long)P * P;
    for (int c = 0; c < NC; c++) {
        __syncthreads();
        const float* lg = logits + (long)(n * NC + c) * H * W;
        for (int i = tid; i < 384; i += 192) {
            int r = i >> 7, j = i & 127;
            float4 v = make_float4(0.f, 0.f, 0.f, 0.f);
            if (rv[r]) v = ((const float4*)(lg + (long)(y0 + r) * W))[j];
            *(float4*)(&slog[r][4 + 4 * j]) = v;
        }
        __syncthreads();
        if (act) {
            float mla = 0.f, mv = -1e30f;
            float lin = 0.f, prod = 1.f;
#pragma unroll
            for (int k = 0; k < 9; k++) {
                int r = k / 3, dx = k % 3;
                float xv = slog[r][3 * px + 3 + dx];
                float m  = mk[k];
                float t1 = (lab[k] == c) ? m : 0.f;
                lin = fmaf(fmaxf(xv, 0.f), m, lin);
                lin = fmaf(-xv, t1, lin);
                float e = __expf(-fabsf(xv));
                prod *= (m > 0.f) ? (1.f + e) : 1.f;   // batch the 9 logs
                mla = fmaxf(mla, t1);
                mv  = fmaxf(mv, (m > 0.f) ? xv : -1e30f);
            }
            bce_part += lin + __logf(prod);            // ONE log per window
            float em  = __expf(-fabsf(mv));
            float rc  = __fdividef(1.f, 1.f + em);
            float sig = (mv >= 0.f) ? rc : em * rc;    // mv=-1e30 -> 0
            long o = (long)(n * NC + c) * ppp + (long)py * P + px;
            g_la[o] = mla;
            g_pr[o] = sig + CLIP_MIN;
        }
    }

#pragma unroll
    for (int off = 16; off > 0; off >>= 1) {
        bce_part   += __shfl_down_sync(0xffffffffu, bce_part,   off);
        valid_part += __shfl_down_sync(0xffffffffu, valid_part, off);
    }
    int wid = tid >> 5, lane = tid & 31;
    if (lane == 0) { warp_b[wid] = bce_part; warp_v[wid] = valid_part; }
    __syncthreads();
    if (tid == 0) {
        float b = 0.f, v = 0.f;
#pragma unroll
        for (int w = 0; w < 6; w++) { b += warp_b[w]; v += warp_v[w]; }
        g_part[bid] = make_float2(b, v);   // plain store, no init needed
    }
}

// ---------------------------------------------------------------------------
// f32x2 helpers
__device__ __forceinline__ ull pk2(float lo, float hi) {
    ull r; asm("mov.b64 %0, {%1, %2};" : "=l"(r) : "f"(lo), "f"(hi)); return r;
}
#define FMA2(d, a, b) asm("fma.rn.f32x2 %0, %1, %2, %0;" : "+l"(d) : "l"(a), "l"(b))

// One step: acc[j*9+l*3+m] += PA[l-pos] * dup(Bj[m-pos])
#define DOSTEP(PL0, PL1, PL2, B00, B01, B02, B10, B11, B12) do {              \
    ull d00 = pk2((B00),(B00)), d01 = pk2((B01),(B01)), d02 = pk2((B02),(B02)); \
    ull d10 = pk2((B10),(B10)), d11 = pk2((B11),(B11)), d12 = pk2((B12),(B12)); \
    FMA2(acc[0],  PL0, d00); FMA2(acc[1],  PL0, d01); FMA2(acc[2],  PL0, d02); \
    FMA2(acc[3],  PL1, d00); FMA2(acc[4],  PL1, d01); FMA2(acc[5],  PL1, d02); \
    FMA2(acc[6],  PL2, d00); FMA2(acc[7],  PL2, d01); FMA2(acc[8],  PL2, d02); \
    FMA2(acc[9],  PL0, d10); FMA2(acc[10], PL0, d11); FMA2(acc[11], PL0, d12); \
    FMA2(acc[12], PL1, d10); FMA2(acc[13], PL1, d11); FMA2(acc[14], PL1, d12); \
    FMA2(acc[15], PL2, d10); FMA2(acc[16], PL2, d11); FMA2(acc[17], PL2, d12); \
} while (0)

#define PAW(t) ((t) < 4 ? PA[(t)]  : PAn[(t) - 4])
#define B0W(t) ((t) < 4 ? b0c[(t)] : b0n[(t) - 4])
#define B1W(t) ((t) < 4 ? b1c[(t)] : b1n[(t) - 4])

// Gram matrix of the 18 shifted views via 6 stream-pair-blocks; also folds in
// the per-view first-moment sums (row-total minus edges trick).
__global__ void __launch_bounds__(96, 6) k_cov() {
    int p     = blockIdx.x;
    int strip = blockIdx.y;
    int ys = strip * SH;
    int sh = min(SH, NH - ys);

    __shared__ __align__(16) float sbuf[2 * 18 * SPITCH];  // la rows | pr rows
    __shared__ float srs[36];
    float* sla = sbuf;
    float* spr = sbuf + 18 * SPITCH;

    int tid = threadIdx.x;
    int row = tid & 15;
    int pb  = tid >> 4;
    const float* la = g_la + p * P * P;
    const float* pr = g_pr + p * P * P;

    int nrows = sh + 2;
    for (int i = tid; i < nrows * P; i += 96) {
        int r = i / P, x = i - r * P;
        sla[r * SPITCH + x] = la[(ys + r) * P + x];
        spr[r * SPITCH + x] = pr[(ys + r) * P + x];
    }
    __syncthreads();

    ull acc[18];
#pragma unroll
    for (int k = 0; k < 18; k++) acc[k] = 0ULL;

    if (row < sh) {
        int gi = c_PBI[pb], gj = c_PBJ[pb];
        int sA0 = 2 * gi, sA1 = 2 * gi + 1, sB0 = 2 * gj, sB1 = 2 * gj + 1;
        const float* pA0 = ((sA0 < 3) ? sla : spr) + ((sA0 < 3 ? sA0 : sA0 - 3) + row) * SPITCH;
        const float* pA1 = ((sA1 < 3) ? sla : spr) + ((sA1 < 3 ? sA1 : sA1 - 3) + row) * SPITCH;
        const float* pB0 = ((sB0 < 3) ? sla : spr) + ((sB0 < 3 ? sB0 : sB0 - 3) + row) * SPITCH;
        const float* pB1 = ((sB1 < 3) ? sla : spr) + ((sB1 < 3 ? sB1 : sB1 - 3) + row) * SPITCH;

        float4 va = *(const float4*)(pA0);
        float4 vb = *(const float4*)(pA1);
        ull PA[4] = { pk2(va.x, vb.x), pk2(va.y, vb.y), pk2(va.z, vb.z), pk2(va.w, vb.w) };
        float4 v0 = *(const float4*)(pB0);
        float4 v1 = *(const float4*)(pB1);
        float b0c[4] = { v0.x, v0.y, v0.z, v0.w };
        float b1c[4] = { v1.x, v1.y, v1.z, v1.w };

        for (int x = 0; x + 4 <= NH - 1; x += 4) {   // steps 0..167
            va = *(const float4*)(pA0 + x + 4);
            vb = *(const float4*)(pA1 + x + 4);
            ull PAn[4] = { pk2(va.x, vb.x), pk2(va.y, vb.y), pk2(va.z, vb.z), pk2(va.w, vb.w) };
            v0 = *(const float4*)(pB0 + x + 4);
            v1 = *(const float4*)(pB1 + x + 4);
            float b0n[4] = { v0.x, v0.y, v0.z, v0.w };
            float b1n[4] = { v1.x, v1.y, v1.z, v1.w };
#pragma unroll
            for (int s = 0; s < 4; s++)
                DOSTEP(PAW(s), PAW(s + 1), PAW(s + 2),
                       B0W(s), B0W(s + 1), B0W(s + 2),
                       B1W(s), B1W(s + 1), B1W(s + 2));
#pragma unroll
            for (int t = 0; t < 4; t++) { PA[t] = PAn[t]; b0c[t] = b0n[t]; b1c[t] = b1n[t]; }
        }
        // tail step x = 168 (positions 168..170)
        DOSTEP(PA[0], PA[1], PA[2], b0c[0], b0c[1], b0c[2], b1c[0], b1c[1], b1c[2]);
    }

    // ---- folded first-moment sums (row totals minus edge elements) ----
    if (tid < 36) {
        int mp = tid / 18, r = tid % 18;
        float T = 0.f;
        if (r < sh + 2) {
            const float* rowp = (mp ? spr : sla) + r * SPITCH;
            for (int x = 0; x < P; x++) T += rowp[x];
        }
        srs[tid] = T;
    }
    __syncthreads();
    if (tid < 18) {
        int mp = tid / 9, dd = tid % 9, dy = dd / 3, dx = dd % 3;
        const float* base = mp ? spr : sla;
        float part = 0.f;
        for (int yl = 0; yl < sh; yl++) {
            int r = yl + dy;
            const float* rowp = base + r * SPITCH;
            float T = srs[mp * 18 + r];
            float rs = (dx == 0) ? T - rowp[169] - rowp[170]
                     : (dx == 1) ? T - rowp[0]   - rowp[170]
                     :             T - rowp[0]   - rowp[1];
            part += rs;
        }
        atomicAdd(&g_sums[p * 18 + tid], (double)part);
    }
    __syncthreads();

    // ---- reduce 96x36 partials over the 16 rows, flush to g_S ----
    float* red = sbuf;             // overlay (96*36 floats)
#pragma unroll
    for (int k = 0; k < 18; k++) {
        float lo, hi;
        asm("mov.b64 {%0, %1}, %2;" : "=f"(lo), "=f"(hi) : "l"(acc[k]));
        red[tid * 36 + k]      = lo;   // i = 0 (stream 2gi)
        red[tid * 36 + 18 + k] = hi;   // i = 1 (stream 2gi+1)
    }
    __syncthreads();
    for (int o = tid; o < 216; o += 96) {
        int pb2 = o / 36, q = o % 36;
        float ssum = 0.f;
#pragma unroll
        for (int r2 = 0; r2 < 16; r2++) ssum += red[(pb2 * 16 + r2) * 36 + q];
        int i = q / 18, k = q % 18;
        int j = k / 9, l = (k % 9) / 3, m = k % 3;
        int a = (2 * c_PBI[pb2] + i) * 3 + l;
        int b = (2 * c_PBJ[pb2] + j) * 3 + m;
        atomicAdd(&g_S[p * 324 + a * 18 + b], (double)ssum);
    }
}

// ---------------------------------------------------------------------------
// Warp-parallel 9x9 Cholesky (fp32; matrices are well-conditioned)
__device__ __forceinline__ void chol9f(float* A, int lane) {
    for (int k = 0; k < 9; k++) {
        if (lane == 0) A[k * 9 + k] = sqrtf(A[k * 9 + k]);
        __syncwarp();
        float rd = __fdividef(1.f, A[k * 9 + k]);
        if (lane > k && lane < 9) A[lane * 9 + k] *= rd;
        __syncwarp();
        for (int idx = lane; idx < 81; idx += 32) {
            int i = idx / 9, j = idx % 9;
            if (j > k && j <= i) A[i * 9 + j] -= A[i * 9 + k] * A[j * 9 + k];
        }
        __syncwarp();
    }
}

// One warp per (n,c): assemble covariances in double, solve in float (proven
// R4 path, 12.7us measured).
__global__ void __launch_bounds__(32) k_solve() {
    int p    = blockIdx.x;
    int lane = threadIdx.x;
    __shared__ float A[81], B[81], C2[81], V[81];
    const double* S  = g_S    + p * 324;
    const double* sm = g_sums + p * 18;
    const double invM = 1.0 / (double)MM;
    for (int idx = lane; idx < 81; idx += 32) {
        int i = idx / 9, j = idx % 9;
        int a = 9 + i, b = 9 + j;
        int hi = a > b ? a : b, lo = a > b ? b : a;
        A[idx] = (float)(S[hi * 18 + lo] - sm[a] * sm[b] * invM + (i == j ? D_ALPHA : 0.0));
        B[idx] = (float)(S[(9 + j) * 18 + i] - sm[i] * sm[9 + j] * invM);   // cross[d][e]
        hi = i > j ? i : j; lo = i > j ? j : i;
        C2[idx] = (float)(S[hi * 18 + lo] - sm[i] * sm[j] * invM);          // la_cov
    }
    __syncwarp();
    chol9f(A, lane);
    if (lane < 9) {   // forward solve L V = cross^T (column d per lane)
        int d = lane;
        for (int e = 0; e < 9; e++) {
            float t = B[d * 9 + e];
            for (int j = 0; j < e; j++) t -= A[e * 9 + j] * V[j * 9 + d];
            V[e * 9 + d] = t * __fdividef(1.f, A[e * 9 + e]);
        }
    }
    __syncwarp();
    for (int idx = lane; idx < 81; idx += 32) {   // appro_var = la_cov - V^T V + aI
        int i = idx / 9, j = idx % 9;
        float t = C2[idx];
#pragma unroll
        for (int k = 0; k < 9; k++) t -= V[k * 9 + i] * V[k * 9 + j];
        if (i == j) t += (float)D_ALPHA;
        B[idx] = t;
    }
    __syncwarp();
    chol9f(B, lane);
    float lsum = (lane < 9) ? logf(B[lane * 9 + lane]) : 0.f;   // 0.5*logdet
    for (int off = 16; off > 0; off >>= 1)
        lsum += __shfl_down_sync(0xffffffffu, lsum, off);
    if (lane == 0) g_rmi[p] = (double)lsum;
}

// ---------------------------------------------------------------------------
// Final: reduce rmi + per-block bce/valid partials (power-of-2, 128 threads).
__global__ void __launch_bounds__(128) k_final(float* __restrict__ out) {
    int t = threadIdx.x;
    __shared__ double sr[128], sb[128], sv[128];
    double rs = 0.0, bs = 0.0, vs = 0.0;
    if (t < NPROB) rs = g_rmi[t];
    for (int i = t; i < NBLK; i += 128) {
        float2 pv = g_part[i];
        bs += (double)pv.x; vs += (double)pv.y;
    }
    sr[t] = rs; sb[t] = bs; sv[t] = vs;
    __syncthreads();
#pragma unroll
    for (int s = 64; s > 0; s >>= 1) {
        if (t < s) { sr[t] += sr[t + s]; sb[t] += sb[t + s]; sv[t] += sv[t + s]; }
        __syncthreads();
    }
    if (t == 0) {
        double rmi = sr[0] / 36.0;                  // mean over batch(4)/half_d(9)
        double bce = sb[0] / (sv[0] + 1.0);
        out[0] = (float)(0.5 * bce + 0.5 * rmi);
    }
}

// ---------------------------------------------------------------------------
extern "C" void kernel_launch(void* const* d_in, const int* in_sizes, int n_in,
                              void* d_out, int out_size) {
    const float* logits = (const float*)d_in[0];
    const int*   labels = (const int*)d_in[1];
    float* out = (float*)d_out;

    k_pool_bce<<<dim3(P, BN), 192>>>(logits, labels);
    k_cov<<<dim3(NPROB, NSTRIP), 96>>>();
    k_solve<<<NPROB, 32>>>();
    k_final<<<1, 128>>>(out);
}